// round 7
// baseline (speedup 1.0000x reference)
#include <cuda_runtime.h>
#include <cstdint>

// DeltaModulationEncoder, round 6: comparison-free recurrence.
// Exact {0,1} indicators via power-of-2 scaled FFMA + clamp:
//   d   = x - recon                         FADD   (+4)
//   a   = fma(d,  2^100, -th*2^100)         FFMA   (+4)  sign(a)==sign(d-th) EXACT
//   b   = fma(d, -2^100, -th*2^100)                      sign(b)==sign(-d-th) EXACT (parallel)
//   p   = min(max(a,0),1)  in {0,1} exact   FMNMX  (+8)  (|d-th| nonzero => >=2^-27 => a>=2^73)
//   m   = min(max(b,0),1)  in {0,1} exact          (parallel)
//   net = p - m            == output spike  FADD   (+4)
//   recon = fma(net, th, recon)             FFMA   (+4)  exact +-0.1f step
// Chain = 24 cyc/step, 9 fixed-latency instrs, no predicates/selects anywhere.
//
// th*2^100 is EXACT: th = 13421773*2^-27, power-of-2 scale preserves mantissa.
// Lane = row (4096 rows), 128 blocks x 32 threads; each lane streams its 32KB
// row with a one-line (8 x float4) prefetch covering DRAM latency.

#define TT 8192
#define NITER (TT / 32)   // 256

__global__ void __launch_bounds__(32, 1)
delta_mod_kernel(const float* __restrict__ x, float* __restrict__ out, int rows)
{
    const int row = blockIdx.x * 32 + threadIdx.x;
    if (row >= rows) return;

    const float4* __restrict__ px = reinterpret_cast<const float4*>(x + (size_t)row * TT);
    float4* __restrict__ po       = reinterpret_cast<float4*>(out + (size_t)row * TT);

    const float TH   = 0.1f;                              // 0x3DCCCCCD
    const float BIG  = 1.2676506002282294e30f;            // 2^100, 0x71800000
    const float NBIG = -1.2676506002282294e30f;
    const float NTHB = __uint_as_float(0xEFCCCCCDu);      // -(0.1f * 2^100), exact

    float recon = 0.0f;

    float4 buf[8];
#pragma unroll
    for (int j = 0; j < 8; ++j) buf[j] = px[j];

    for (int it = 0; it < NITER; ++it) {
        const int nxt = (it + 1 < NITER) ? (it + 1) : (NITER - 1);

#pragma unroll
        for (int j = 0; j < 8; ++j) {
            float4 c = buf[j];
            buf[j] = px[nxt * 8 + j];   // prefetch next line's chunk (off chain)

            float4 o;

            {
                float d = c.x - recon;
                float a = fmaf(d, BIG,  NTHB);
                float b = fmaf(d, NBIG, NTHB);
                float p = fminf(fmaxf(a, 0.0f), 1.0f);
                float m = fminf(fmaxf(b, 0.0f), 1.0f);
                float net = p - m;
                recon = fmaf(net, TH, recon);
                o.x = net;
            }
            {
                float d = c.y - recon;
                float a = fmaf(d, BIG,  NTHB);
                float b = fmaf(d, NBIG, NTHB);
                float p = fminf(fmaxf(a, 0.0f), 1.0f);
                float m = fminf(fmaxf(b, 0.0f), 1.0f);
                float net = p - m;
                recon = fmaf(net, TH, recon);
                o.y = net;
            }
            {
                float d = c.z - recon;
                float a = fmaf(d, BIG,  NTHB);
                float b = fmaf(d, NBIG, NTHB);
                float p = fminf(fmaxf(a, 0.0f), 1.0f);
                float m = fminf(fmaxf(b, 0.0f), 1.0f);
                float net = p - m;
                recon = fmaf(net, TH, recon);
                o.z = net;
            }
            {
                float d = c.w - recon;
                float a = fmaf(d, BIG,  NTHB);
                float b = fmaf(d, NBIG, NTHB);
                float p = fminf(fmaxf(a, 0.0f), 1.0f);
                float m = fminf(fmaxf(b, 0.0f), 1.0f);
                float net = p - m;
                recon = fmaf(net, TH, recon);
                o.w = net;
            }

            po[it * 8 + j] = o;   // off-chain store
        }
    }
}

extern "C" void kernel_launch(void* const* d_in, const int* in_sizes, int n_in,
                              void* d_out, int out_size)
{
    const float* x = (const float*)d_in[0];
    float* out = (float*)d_out;

    const int rows = in_sizes[0] / TT;      // 4096
    const int blocks = (rows + 31) / 32;    // 128

    delta_mod_kernel<<<blocks, 32>>>(x, out, rows);
}

// round 12
// speedup vs baseline: 1.6706x; 1.6706x over previous
#include <cuda_runtime.h>
#include <cstdint>

// DeltaModulationEncoder, rounds 8-12: cp.async smem-staged input pipeline.
//
// Diagnosis: rounds 2/6/7 showed a constant ~30 cyc/step gap over the compute
// chain theory, independent of formulation => the register double-buffer's
// scoreboard/WAR coupling (shared SB slot across the 8 in-flight LDGs) exposes
// DRAM latency every iteration. Fix: LDGSTS (cp.async) into shared memory with
// explicit commit_group/wait_group, 3 lines in flight, consumed 3 iterations
// (~1300+ cyc) after issue. No register WAR on loads, precise group waits.
//
// Compute (best measured, R6, bit-exact):
//   d = x - recon; p = set.gt(d,th); m = set.lt(d,-th);   (FSET -> 1.0/0.0)
//   net = p - m (output);  recon = fma(net, th, recon)    (exact +-0.1f step)
//
// smem [stage][chunk][thread]: LDS.128 conflict-free (8 lanes/phase = 32 banks).

#define TT     8192
#define NITER  (TT / 32)   // 256 lines of 32 steps (128B per row per line)
#define STAGES 4           // ring slots; 3 lines in flight

__device__ __forceinline__ float fset_gt(float a, float b) {
    float r; asm("set.gt.f32.f32 %0, %1, %2;" : "=f"(r) : "f"(a), "f"(b)); return r;
}
__device__ __forceinline__ float fset_lt(float a, float b) {
    float r; asm("set.lt.f32.f32 %0, %1, %2;" : "=f"(r) : "f"(a), "f"(b)); return r;
}

__device__ __forceinline__ void cp_async16(uint32_t smem_dst, const void* gsrc) {
    asm volatile("cp.async.cg.shared.global [%0], [%1], 16;\n"
                 :: "r"(smem_dst), "l"(gsrc) : "memory");
}
__device__ __forceinline__ void cp_commit() {
    asm volatile("cp.async.commit_group;\n" ::: "memory");
}
__device__ __forceinline__ void cp_wait2() {
    asm volatile("cp.async.wait_group 2;\n" ::: "memory");
}

#define STEP(XV, OV)                                   \
    {                                                  \
        float d   = (XV) - recon;                      \
        float p   = fset_gt(d, TH);                    \
        float m   = fset_lt(d, NTH);                   \
        float net = p - m;                             \
        recon     = fmaf(net, TH, recon);              \
        (OV)      = net;                               \
    }

__global__ void __launch_bounds__(32, 1)
delta_mod_kernel(const float* __restrict__ x, float* __restrict__ out, int rows)
{
    __shared__ float4 sb[STAGES][8][32];   // 16 KB

    const int tid = threadIdx.x;
    const int row = blockIdx.x * 32 + tid;
    if (row >= rows) return;

    const float* __restrict__ gx = x + (size_t)row * TT;
    float4* __restrict__ po      = reinterpret_cast<float4*>(out + (size_t)row * TT);

    const float TH  = 0.1f;    // 0x3DCCCCCD == jnp.float32(0.1)
    const float NTH = -0.1f;

    // smem byte address of this thread's slot base
    const uint32_t sbase = (uint32_t)__cvta_generic_to_shared(&sb[0][0][tid]);
    // address of [stage][chunk][tid] = sbase + ((stage*8 + chunk) * 32) * 16

    // ---- prologue: stage lines 0..2 ----
#pragma unroll
    for (int s = 0; s < 3; ++s) {
#pragma unroll
        for (int j = 0; j < 8; ++j) {
            cp_async16(sbase + (uint32_t)(((s * 8 + j) * 32) * 16),
                       gx + s * 32 + j * 4);
        }
        cp_commit();
    }

    float recon = 0.0f;

    for (int it = 0; it < NITER; ++it) {
        cp_wait2();                       // line `it` (group it) retired

        const int slot = it & (STAGES - 1);
        const int dsl  = (it + 3) & (STAGES - 1);
        const int nl   = (it + 3 < NITER) ? (it + 3) : (NITER - 1);  // clamped refill

        // preload first chunk of this line (one exposed LDS per 32 steps)
        float4 c = sb[slot][0][tid];

#pragma unroll
        for (int j = 0; j < 8; ++j) {
            // refill one chunk of line it+3 into the free slot (interleaved issue)
            cp_async16(sbase + (uint32_t)(((dsl * 8 + j) * 32) * 16),
                       gx + nl * 32 + j * 4);

            // lookahead next chunk from smem (off-chain)
            float4 cn;
            if (j < 7) cn = sb[slot][j + 1][tid];

            float4 o;
            STEP(c.x, o.x)
            STEP(c.y, o.y)
            STEP(c.z, o.z)
            STEP(c.w, o.w)

            po[it * 8 + j] = o;           // off-chain store

            if (j < 7) c = cn;
        }

        cp_commit();                      // group for line it+3
    }
}

extern "C" void kernel_launch(void* const* d_in, const int* in_sizes, int n_in,
                              void* d_out, int out_size)
{
    const float* x = (const float*)d_in[0];
    float* out = (float*)d_out;

    const int rows   = in_sizes[0] / TT;     // 4096
    const int blocks = (rows + 31) / 32;     // 128

    delta_mod_kernel<<<blocks, 32>>>(x, out, rows);
}

// round 13
// speedup vs baseline: 1.6710x; 1.0002x over previous
#include <cuda_runtime.h>
#include <cstdint>

// DeltaModulationEncoder, round 13: cp.async pipeline (R12, measured win)
// + predicate-free clamp compute (R7, measured bit-exact).
//
// R12 showed ~31 cyc/step == FADD + FSETP(13 pred-arm) + SEL + FADD + FFMA:
// PTX set.gt lowers to FSETP+SEL, putting predicate latency on the chain.
// Replace with exact FFMA/FMNMX indicator (all 4-cyc fixed-lat, chain 24):
//   d   = x - recon
//   a   = fma(d,  2^100, -th*2^100)   sign(d-th) exact (Sterbenz => |.|>=2^73)
//   b   = fma(d, -2^100, -th*2^100)   sign(-d-th) exact   (parallel)
//   p   = min(max(a,0),1) in {0,1}    m likewise          (parallel)
//   net = p - m  (output);  recon = fma(net, th, recon)   (exact +-0.1f)
//
// Pipeline: cp.async -> smem ring, 4 stages, 3 lines in flight, wait_group 2.
// smem [stage][chunk][thread]: LDS.128 conflict-free.

#define TT     8192
#define NITER  (TT / 32)   // 256 lines of 32 steps
#define STAGES 4

__device__ __forceinline__ void cp_async16(uint32_t smem_dst, const void* gsrc) {
    asm volatile("cp.async.cg.shared.global [%0], [%1], 16;\n"
                 :: "r"(smem_dst), "l"(gsrc) : "memory");
}
__device__ __forceinline__ void cp_commit() {
    asm volatile("cp.async.commit_group;\n" ::: "memory");
}
__device__ __forceinline__ void cp_wait2() {
    asm volatile("cp.async.wait_group 2;\n" ::: "memory");
}

#define STEP(XV, OV)                                       \
    {                                                      \
        float d   = (XV) - recon;                          \
        float a   = fmaf(d, BIG,  NTHB);                   \
        float b   = fmaf(d, NBIG, NTHB);                   \
        float p   = fminf(fmaxf(a, 0.0f), 1.0f);           \
        float m   = fminf(fmaxf(b, 0.0f), 1.0f);           \
        float net = p - m;                                 \
        recon     = fmaf(net, TH, recon);                  \
        (OV)      = net;                                   \
    }

__global__ void __launch_bounds__(32, 1)
delta_mod_kernel(const float* __restrict__ x, float* __restrict__ out, int rows)
{
    __shared__ float4 sb[STAGES][8][32];   // 16 KB

    const int tid = threadIdx.x;
    const int row = blockIdx.x * 32 + tid;
    if (row >= rows) return;

    const float* __restrict__ gx = x + (size_t)row * TT;
    float4* __restrict__ po      = reinterpret_cast<float4*>(out + (size_t)row * TT);

    const float TH   = 0.1f;                           // 0x3DCCCCCD
    const float BIG  = 1.2676506002282294e30f;         // 2^100
    const float NBIG = -1.2676506002282294e30f;
    const float NTHB = __uint_as_float(0xEFCCCCCDu);   // -(0.1f * 2^100), exact

    const uint32_t sbase = (uint32_t)__cvta_generic_to_shared(&sb[0][0][tid]);

    // ---- prologue: stage lines 0..2 ----
#pragma unroll
    for (int s = 0; s < 3; ++s) {
#pragma unroll
        for (int j = 0; j < 8; ++j) {
            cp_async16(sbase + (uint32_t)(((s * 8 + j) * 32) * 16),
                       gx + s * 32 + j * 4);
        }
        cp_commit();
    }

    float recon = 0.0f;

    for (int it = 0; it < NITER; ++it) {
        cp_wait2();                       // line `it` retired

        const int slot = it & (STAGES - 1);
        const int dsl  = (it + 3) & (STAGES - 1);
        const int nl   = (it + 3 < NITER) ? (it + 3) : (NITER - 1);

        float4 c = sb[slot][0][tid];      // one exposed LDS per 32 steps

#pragma unroll
        for (int j = 0; j < 8; ++j) {
            cp_async16(sbase + (uint32_t)(((dsl * 8 + j) * 32) * 16),
                       gx + nl * 32 + j * 4);

            float4 cn;
            if (j < 7) cn = sb[slot][j + 1][tid];   // off-chain lookahead

            float4 o;
            STEP(c.x, o.x)
            STEP(c.y, o.y)
            STEP(c.z, o.z)
            STEP(c.w, o.w)

            po[it * 8 + j] = o;           // off-chain store

            if (j < 7) c = cn;
        }

        cp_commit();                      // group for line it+3
    }
}

extern "C" void kernel_launch(void* const* d_in, const int* in_sizes, int n_in,
                              void* d_out, int out_size)
{
    const float* x = (const float*)d_in[0];
    float* out = (float*)d_out;

    const int rows   = in_sizes[0] / TT;     // 4096
    const int blocks = (rows + 31) / 32;     // 128

    delta_mod_kernel<<<blocks, 32>>>(x, out, rows);
}